// round 9
// baseline (speedup 1.0000x reference)
#include <cuda_runtime.h>
#include <cuda_bf16.h>
#include <cstdint>

#define S 1024
#define B 8192
#define EPSF 1e-8f
#define THREADS 256
#define ROWS_PER_BLOCK 2
#define SEG 256
#define LPT 8
#define NBLK (B / ROWS_PER_BLOCK)   // 4096

__device__ float g_ga[S];   // gamma*lam
__device__ float g_gb[S];   // gamma*(1-lam)

__global__ void setup_kernel(const float* __restrict__ raw_gamma,
                             const float* __restrict__ raw_lambd)
{
    const float gamma = fmaxf(tanhf(raw_gamma[0]), EPSF);
    int i = threadIdx.x;
    float lam = fmaxf(tanhf(raw_lambd[i]), EPSF);
    g_ga[i] = gamma * lam;
    g_gb[i] = gamma * (1.0f - lam);
}

__device__ __forceinline__ void cp_async4(void* smem_dst, const void* gmem_src) {
    unsigned int s = (unsigned int)__cvta_generic_to_shared(smem_dst);
    asm volatile("cp.async.ca.shared.global [%0], [%1], 4;" :: "r"(s), "l"(gmem_src));
}

// Two-level parallel reverse affine scan: 4 warps per row, one straight-line
// 256-step segment per warp. v AND dones staged via cp.async to cut in-flight
// register pressure; launch_bounds caps regs at 40 for 6 blocks/SM.
__global__ __launch_bounds__(THREADS, 6)
void td_lambda_kernel(const float* __restrict__ values,
                      const float* __restrict__ rewards,
                      const int*   __restrict__ dones,
                      float* __restrict__ out)
{
    __shared__ float s_v[8][SEG + 8];   // per-warp staged values (padded)
    __shared__ int   s_d[8][SEG + 8];   // per-warp staged dones (padded)
    __shared__ float s_cA[8], s_cB[8];  // per-warp segment composites

    const int tid  = threadIdx.x;
    const int lane = tid & 31;
    const int warp = tid >> 5;

    if (blockIdx.x < NBLK) {
        const int row_in_blk = warp >> 2;
        const int seg        = warp & 3;
        const int b = blockIdx.x * ROWS_PER_BLOCK + row_in_blk;
        const float* __restrict__ rrow = rewards + (size_t)b * S;
        const int*   __restrict__ drow = dones   + (size_t)b * S;
        const float* __restrict__ vrow = values  + (size_t)b * (S + 1);
        float* __restrict__ orow = out + (size_t)b * S;

        const int segbase = seg * SEG;
        const int base    = segbase + lane * LPT;

        // ---- v and d: gmem -> padded smem via cp.async (no registers held) ----
        #pragma unroll
        for (int k = 0; k < 8; ++k)
            cp_async4(&s_v[warp][lane + 33 * k],
                      vrow + segbase + 1 + lane + 32 * k);
        #pragma unroll
        for (int k = 0; k < 8; ++k)
            cp_async4(&s_d[warp][lane + 33 * k],
                      drow + segbase + lane + 32 * k);
        asm volatile("cp.async.commit_group;");

        // ---- r/table loads in flight while the copies run ----
        float4 r0 = *(const float4*)(rrow + base);
        float4 r1 = *(const float4*)(rrow + base + 4);
        float4 ga0 = *(const float4*)(g_ga + base);
        float4 ga1 = *(const float4*)(g_ga + base + 4);
        float4 gb0 = *(const float4*)(g_gb + base);
        float4 gb1 = *(const float4*)(g_gb + base + 4);
        const float vS = __ldg(&vrow[S]);

        asm volatile("cp.async.wait_group 0;");
        __syncwarp();

        float r[LPT]  = {r0.x, r0.y, r0.z, r0.w, r1.x, r1.y, r1.z, r1.w};
        float ga[LPT] = {ga0.x, ga0.y, ga0.z, ga0.w, ga1.x, ga1.y, ga1.z, ga1.w};
        float gb[LPT] = {gb0.x, gb0.y, gb0.z, gb0.w, gb1.x, gb1.y, gb1.z, gb1.w};
        const int   pofs = lane * LPT + (lane >> 2);          // conflict-free view
        const float* vbuf = &s_v[warp][pofs];
        const int*   dbuf = &s_d[warp][pofs];

        float a[LPT], bb[LPT];
        #pragma unroll
        for (int j = 0; j < LPT; ++j) {
            float v = vbuf[j];
            bool  z = (dbuf[j] != 0);
            a[j]  = z ? 0.0f : ga[j];
            bb[j] = z ? r[j] : fmaf(gb[j], v, r[j]);
        }

        // local composition G = F_j0 ∘ ... ∘ F_j7
        float A = a[LPT - 1], Bc = bb[LPT - 1];
        #pragma unroll
        for (int j = LPT - 2; j >= 0; --j) {
            Bc = fmaf(a[j], Bc, bb[j]);
            A  = a[j] * A;
        }

        // warp suffix scan of lane composites
        float sA = A, sB = Bc;
        #pragma unroll
        for (int off = 1; off < 32; off <<= 1) {
            float a2 = __shfl_down_sync(0xffffffffu, sA, off);
            float b2 = __shfl_down_sync(0xffffffffu, sB, off);
            if (lane + off < 32) {
                sB = fmaf(sA, b2, sB);
                sA = sA * a2;
            }
        }

        if (lane == 0) { s_cA[warp] = sA; s_cB[warp] = sB; }
        __syncthreads();

        // entry carry: apply later segments' composites to v_S (≤3 FMAs)
        float carry = vS;
        #pragma unroll
        for (int k = 3; k >= 1; --k) {
            if (k > seg) {
                int w = (row_in_blk << 2) | k;
                carry = fmaf(s_cA[w], carry, s_cB[w]);
            }
        }

        float eA = __shfl_down_sync(0xffffffffu, sA, 1);
        float eB = __shfl_down_sync(0xffffffffu, sB, 1);
        if (lane == 31) { eA = 1.0f; eB = 0.0f; }
        float x = fmaf(eA, carry, eB);

        float o[LPT];
        #pragma unroll
        for (int j = LPT - 1; j >= 0; --j) {
            x = fmaf(a[j], x, bb[j]);
            o[j] = x;
        }
        *(float4*)(orow + base)     = make_float4(o[0], o[1], o[2], o[3]);
        *(float4*)(orow + base + 4) = make_float4(o[4], o[5], o[6], o[7]);
    } else {
        // ---------------- srw (sum_reward_weights) ----------------
        float* s_w    = &s_v[0][0];
        float* s_part = &s_v[4][0];

        if (tid < 32) {
            float carry = 1.0f;
            for (int c = S / 32 - 1; c >= 0; --c) {
                const int t = c * 32 + lane;
                float a  = g_ga[t];
                float bb = g_gb[t];
                #pragma unroll
                for (int off = 1; off < 32; off <<= 1) {
                    float a2 = __shfl_down_sync(0xffffffffu, a,  off);
                    float b2 = __shfl_down_sync(0xffffffffu, bb, off);
                    if (lane + off < 32) {
                        bb = fmaf(a, b2, bb);
                        a  = a * a2;
                    }
                }
                float vv = fmaf(a, carry, bb);
                s_w[t] = fmaxf(1.0f - vv, EPSF);
                carry = __shfl_sync(0xffffffffu, vv, 0);
            }
        }
        __syncthreads();

        float ps = 0.0f;
        for (int i = tid; i < S; i += THREADS) ps += s_w[i];
        s_part[tid] = ps;
        __syncthreads();
        for (int stride = THREADS / 2; stride > 0; stride >>= 1) {
            if (tid < stride) s_part[tid] += s_part[tid + stride];
            __syncthreads();
        }
        float mean = s_part[0] * (1.0f / (float)S);
        float inv  = 1.0f / fmaxf(mean, EPSF);
        for (int i = tid; i < S; i += THREADS)
            out[(size_t)B * S + i] = s_w[i] * inv;
    }
}

extern "C" void kernel_launch(void* const* d_in, const int* in_sizes, int n_in,
                              void* d_out, int out_size) {
    const float* raw_gamma = (const float*)d_in[0];
    const float* raw_lambd = (const float*)d_in[1];
    const float* values    = (const float*)d_in[2];
    const float* rewards   = (const float*)d_in[3];
    const int*   dones     = (const int*)d_in[4];
    float* out = (float*)d_out;

    setup_kernel<<<1, S>>>(raw_gamma, raw_lambd);
    td_lambda_kernel<<<NBLK + 1, THREADS>>>(values, rewards, dones, out);
}

// round 10
// speedup vs baseline: 1.1495x; 1.1495x over previous
#include <cuda_runtime.h>
#include <cuda_bf16.h>
#include <cstdint>

#define S 1024
#define B 8192
#define EPSF 1e-8f
#define THREADS 256
#define ROWS_PER_BLOCK 2
#define SEG 256
#define LPT 8
#define NBLK (B / ROWS_PER_BLOCK)   // 4096

__device__ float g_ga[S];   // gamma*lam
__device__ float g_gb[S];   // gamma*(1-lam)

__global__ void setup_kernel(const float* __restrict__ raw_gamma,
                             const float* __restrict__ raw_lambd)
{
    const float gamma = fmaxf(tanhf(raw_gamma[0]), EPSF);
    int i = threadIdx.x;
    float lam = fmaxf(tanhf(raw_lambd[i]), EPSF);
    g_ga[i] = gamma * lam;
    g_gb[i] = gamma * (1.0f - lam);
}

__device__ __forceinline__ void cp_async4(void* smem_dst, const void* gmem_src) {
    unsigned int s = (unsigned int)__cvta_generic_to_shared(smem_dst);
    asm volatile("cp.async.ca.shared.global [%0], [%1], 4;" :: "r"(s), "l"(gmem_src));
}

// Two-level parallel reverse affine scan: 4 warps per row, one straight-line
// 256-step segment per warp. v staged via cp.async; r/d via wide streaming
// LDGs (__ldcs); streaming stores (__stcs) — pure one-pass data.
__global__ __launch_bounds__(THREADS)
void td_lambda_kernel(const float* __restrict__ values,
                      const float* __restrict__ rewards,
                      const int*   __restrict__ dones,
                      float* __restrict__ out)
{
    __shared__ float s_v[8][SEG + 8];   // per-warp staged values (padded)
    __shared__ float s_cA[8], s_cB[8];  // per-warp segment composites

    const int tid  = threadIdx.x;
    const int lane = tid & 31;
    const int warp = tid >> 5;

    if (blockIdx.x < NBLK) {
        const int row_in_blk = warp >> 2;
        const int seg        = warp & 3;
        const int b = blockIdx.x * ROWS_PER_BLOCK + row_in_blk;
        const float* __restrict__ rrow = rewards + (size_t)b * S;
        const int*   __restrict__ drow = dones   + (size_t)b * S;
        const float* __restrict__ vrow = values  + (size_t)b * (S + 1);
        float* __restrict__ orow = out + (size_t)b * S;

        const int segbase = seg * SEG;
        const int base    = segbase + lane * LPT;

        // ---- v: gmem -> padded smem via cp.async (no registers held) ----
        #pragma unroll
        for (int k = 0; k < 8; ++k)
            cp_async4(&s_v[warp][lane + 33 * k],
                      vrow + segbase + 1 + lane + 32 * k);
        asm volatile("cp.async.commit_group;");

        // ---- r/d/table loads in flight while the copies run ----
        float4 r0 = __ldcs((const float4*)(rrow + base));
        float4 r1 = __ldcs((const float4*)(rrow + base + 4));
        int4   d0 = __ldcs((const int4*)(drow + base));
        int4   d1 = __ldcs((const int4*)(drow + base + 4));
        float4 ga0 = *(const float4*)(g_ga + base);
        float4 ga1 = *(const float4*)(g_ga + base + 4);
        float4 gb0 = *(const float4*)(g_gb + base);
        float4 gb1 = *(const float4*)(g_gb + base + 4);
        const float vS = __ldg(&vrow[S]);

        asm volatile("cp.async.wait_group 0;");
        __syncwarp();

        float r[LPT]  = {r0.x, r0.y, r0.z, r0.w, r1.x, r1.y, r1.z, r1.w};
        int   dn[LPT] = {d0.x, d0.y, d0.z, d0.w, d1.x, d1.y, d1.z, d1.w};
        float ga[LPT] = {ga0.x, ga0.y, ga0.z, ga0.w, ga1.x, ga1.y, ga1.z, ga1.w};
        float gb[LPT] = {gb0.x, gb0.y, gb0.z, gb0.w, gb1.x, gb1.y, gb1.z, gb1.w};
        const float* vbuf = &s_v[warp][lane * LPT + (lane >> 2)];  // conflict-free

        float a[LPT], bb[LPT];
        #pragma unroll
        for (int j = 0; j < LPT; ++j) {
            float v = vbuf[j];
            bool  z = (dn[j] != 0);
            a[j]  = z ? 0.0f : ga[j];
            bb[j] = z ? r[j] : fmaf(gb[j], v, r[j]);
        }

        // local composition G = F_j0 ∘ ... ∘ F_j7
        float A = a[LPT - 1], Bc = bb[LPT - 1];
        #pragma unroll
        for (int j = LPT - 2; j >= 0; --j) {
            Bc = fmaf(a[j], Bc, bb[j]);
            A  = a[j] * A;
        }

        // warp suffix scan of lane composites
        float sA = A, sB = Bc;
        #pragma unroll
        for (int off = 1; off < 32; off <<= 1) {
            float a2 = __shfl_down_sync(0xffffffffu, sA, off);
            float b2 = __shfl_down_sync(0xffffffffu, sB, off);
            if (lane + off < 32) {
                sB = fmaf(sA, b2, sB);
                sA = sA * a2;
            }
        }

        if (lane == 0) { s_cA[warp] = sA; s_cB[warp] = sB; }
        __syncthreads();

        // entry carry: apply later segments' composites to v_S (≤3 FMAs)
        float carry = vS;
        #pragma unroll
        for (int k = 3; k >= 1; --k) {
            if (k > seg) {
                int w = (row_in_blk << 2) | k;
                carry = fmaf(s_cA[w], carry, s_cB[w]);
            }
        }

        float eA = __shfl_down_sync(0xffffffffu, sA, 1);
        float eB = __shfl_down_sync(0xffffffffu, sB, 1);
        if (lane == 31) { eA = 1.0f; eB = 0.0f; }
        float x = fmaf(eA, carry, eB);

        float o[LPT];
        #pragma unroll
        for (int j = LPT - 1; j >= 0; --j) {
            x = fmaf(a[j], x, bb[j]);
            o[j] = x;
        }
        __stcs((float4*)(orow + base),     make_float4(o[0], o[1], o[2], o[3]));
        __stcs((float4*)(orow + base + 4), make_float4(o[4], o[5], o[6], o[7]));
    } else {
        // ---------------- srw (sum_reward_weights) ----------------
        float* s_w    = &s_v[0][0];
        float* s_part = &s_v[4][0];

        if (tid < 32) {
            float carry = 1.0f;
            for (int c = S / 32 - 1; c >= 0; --c) {
                const int t = c * 32 + lane;
                float a  = g_ga[t];
                float bb = g_gb[t];
                #pragma unroll
                for (int off = 1; off < 32; off <<= 1) {
                    float a2 = __shfl_down_sync(0xffffffffu, a,  off);
                    float b2 = __shfl_down_sync(0xffffffffu, bb, off);
                    if (lane + off < 32) {
                        bb = fmaf(a, b2, bb);
                        a  = a * a2;
                    }
                }
                float vv = fmaf(a, carry, bb);
                s_w[t] = fmaxf(1.0f - vv, EPSF);
                carry = __shfl_sync(0xffffffffu, vv, 0);
            }
        }
        __syncthreads();

        float ps = 0.0f;
        for (int i = tid; i < S; i += THREADS) ps += s_w[i];
        s_part[tid] = ps;
        __syncthreads();
        for (int stride = THREADS / 2; stride > 0; stride >>= 1) {
            if (tid < stride) s_part[tid] += s_part[tid + stride];
            __syncthreads();
        }
        float mean = s_part[0] * (1.0f / (float)S);
        float inv  = 1.0f / fmaxf(mean, EPSF);
        for (int i = tid; i < S; i += THREADS)
            out[(size_t)B * S + i] = s_w[i] * inv;
    }
}

extern "C" void kernel_launch(void* const* d_in, const int* in_sizes, int n_in,
                              void* d_out, int out_size) {
    const float* raw_gamma = (const float*)d_in[0];
    const float* raw_lambd = (const float*)d_in[1];
    const float* values    = (const float*)d_in[2];
    const float* rewards   = (const float*)d_in[3];
    const int*   dones     = (const int*)d_in[4];
    float* out = (float*)d_out;

    setup_kernel<<<1, S>>>(raw_gamma, raw_lambd);
    td_lambda_kernel<<<NBLK + 1, THREADS>>>(values, rewards, dones, out);
}

// round 11
// speedup vs baseline: 1.2424x; 1.0808x over previous
#include <cuda_runtime.h>
#include <cuda_bf16.h>
#include <cstdint>

#define S 1024
#define B 8192
#define EPSF 1e-8f
#define THREADS 256
#define SEG 128              // timesteps per warp segment
#define LPT 4                // timesteps per lane
#define WPR 8                // warps per row
#define NBLK B               // 1 row per block

__device__ float g_ga[S];   // gamma*lam
__device__ float g_gb[S];   // gamma*(1-lam)

__global__ void setup_kernel(const float* __restrict__ raw_gamma,
                             const float* __restrict__ raw_lambd)
{
    const float gamma = fmaxf(tanhf(raw_gamma[0]), EPSF);
    int i = threadIdx.x;
    float lam = fmaxf(tanhf(raw_lambd[i]), EPSF);
    g_ga[i] = gamma * lam;
    g_gb[i] = gamma * (1.0f - lam);
}

__device__ __forceinline__ void cp_async4(void* smem_dst, const void* gmem_src) {
    unsigned int s = (unsigned int)__cvta_generic_to_shared(smem_dst);
    asm volatile("cp.async.ca.shared.global [%0], [%1], 4;" :: "r"(s), "l"(gmem_src));
}

// Two-level parallel reverse affine scan: 8 warps per row, 128-step segment
// per warp, 4 timesteps per lane. Small register tile -> full occupancy.
__global__ __launch_bounds__(THREADS, 8)
void td_lambda_kernel(const float* __restrict__ values,
                      const float* __restrict__ rewards,
                      const int*   __restrict__ dones,
                      float* __restrict__ out)
{
    __shared__ float s_v[WPR][SEG + SEG / 32];   // 8 x 132, padded
    __shared__ float s_cA[WPR], s_cB[WPR];
    __shared__ float s_part[THREADS];            // srw scratch (separate!)

    const int tid  = threadIdx.x;
    const int lane = tid & 31;
    const int warp = tid >> 5;

    if (blockIdx.x < NBLK) {
        const int b   = blockIdx.x;
        const int seg = warp;                    // 0..7
        const float* __restrict__ rrow = rewards + (size_t)b * S;
        const int*   __restrict__ drow = dones   + (size_t)b * S;
        const float* __restrict__ vrow = values  + (size_t)b * (S + 1);
        float* __restrict__ orow = out + (size_t)b * S;

        const int segbase = seg * SEG;
        const int base    = segbase + lane * LPT;

        // ---- v: gmem -> padded smem via cp.async ----
        #pragma unroll
        for (int k = 0; k < 4; ++k)
            cp_async4(&s_v[warp][lane + 33 * k],
                      vrow + segbase + 1 + lane + 32 * k);
        asm volatile("cp.async.commit_group;");

        // ---- r/d/table loads while copies fly ----
        float4 r4 = __ldcs((const float4*)(rrow + base));
        int4   d4 = __ldcs((const int4*)(drow + base));
        float4 ga4 = *(const float4*)(g_ga + base);
        float4 gb4 = *(const float4*)(g_gb + base);
        const float vS = __ldg(&vrow[S]);

        asm volatile("cp.async.wait_group 0;");
        __syncwarp();

        float r[LPT]  = {r4.x, r4.y, r4.z, r4.w};
        int   dn[LPT] = {d4.x, d4.y, d4.z, d4.w};
        float ga[LPT] = {ga4.x, ga4.y, ga4.z, ga4.w};
        float gb[LPT] = {gb4.x, gb4.y, gb4.z, gb4.w};
        // conflict-free: bank(4l + l>>3) distinct over lanes
        const float* vbuf = &s_v[warp][lane * LPT + (lane >> 3)];

        float a[LPT], bb[LPT];
        #pragma unroll
        for (int j = 0; j < LPT; ++j) {
            float v = vbuf[j];
            bool  z = (dn[j] != 0);
            a[j]  = z ? 0.0f : ga[j];
            bb[j] = z ? r[j] : fmaf(gb[j], v, r[j]);
        }

        // local composition G = F_j0 ∘ ... ∘ F_j3
        float A = a[LPT - 1], Bc = bb[LPT - 1];
        #pragma unroll
        for (int j = LPT - 2; j >= 0; --j) {
            Bc = fmaf(a[j], Bc, bb[j]);
            A  = a[j] * A;
        }

        // warp suffix scan of lane composites
        float sA = A, sB = Bc;
        #pragma unroll
        for (int off = 1; off < 32; off <<= 1) {
            float a2 = __shfl_down_sync(0xffffffffu, sA, off);
            float b2 = __shfl_down_sync(0xffffffffu, sB, off);
            if (lane + off < 32) {
                sB = fmaf(sA, b2, sB);
                sA = sA * a2;
            }
        }

        if (lane == 0) { s_cA[warp] = sA; s_cB[warp] = sB; }
        __syncthreads();

        // entry carry: apply composites of segments seg+1..7 to v_S
        float carry = vS;
        #pragma unroll
        for (int k = WPR - 1; k >= 1; --k) {
            if (k > seg)
                carry = fmaf(s_cA[k], carry, s_cB[k]);
        }

        float eA = __shfl_down_sync(0xffffffffu, sA, 1);
        float eB = __shfl_down_sync(0xffffffffu, sB, 1);
        if (lane == 31) { eA = 1.0f; eB = 0.0f; }
        float x = fmaf(eA, carry, eB);

        float o[LPT];
        #pragma unroll
        for (int j = LPT - 1; j >= 0; --j) {
            x = fmaf(a[j], x, bb[j]);
            o[j] = x;
        }
        __stcs((float4*)(orow + base), make_float4(o[0], o[1], o[2], o[3]));
    } else {
        // ---------------- srw (sum_reward_weights) ----------------
        float* s_w = &s_v[0][0];   // 1056 contiguous floats >= S

        if (tid < 32) {
            float carry = 1.0f;
            for (int c = S / 32 - 1; c >= 0; --c) {
                const int t = c * 32 + lane;
                float a  = g_ga[t];
                float bb = g_gb[t];
                #pragma unroll
                for (int off = 1; off < 32; off <<= 1) {
                    float a2 = __shfl_down_sync(0xffffffffu, a,  off);
                    float b2 = __shfl_down_sync(0xffffffffu, bb, off);
                    if (lane + off < 32) {
                        bb = fmaf(a, b2, bb);
                        a  = a * a2;
                    }
                }
                float vv = fmaf(a, carry, bb);
                s_w[t] = fmaxf(1.0f - vv, EPSF);
                carry = __shfl_sync(0xffffffffu, vv, 0);
            }
        }
        __syncthreads();

        float ps = 0.0f;
        for (int i = tid; i < S; i += THREADS) ps += s_w[i];
        s_part[tid] = ps;
        __syncthreads();
        for (int stride = THREADS / 2; stride > 0; stride >>= 1) {
            if (tid < stride) s_part[tid] += s_part[tid + stride];
            __syncthreads();
        }
        float mean = s_part[0] * (1.0f / (float)S);
        float inv  = 1.0f / fmaxf(mean, EPSF);
        for (int i = tid; i < S; i += THREADS)
            out[(size_t)B * S + i] = s_w[i] * inv;
    }
}

extern "C" void kernel_launch(void* const* d_in, const int* in_sizes, int n_in,
                              void* d_out, int out_size) {
    const float* raw_gamma = (const float*)d_in[0];
    const float* raw_lambd = (const float*)d_in[1];
    const float* values    = (const float*)d_in[2];
    const float* rewards   = (const float*)d_in[3];
    const int*   dones     = (const int*)d_in[4];
    float* out = (float*)d_out;

    setup_kernel<<<1, S>>>(raw_gamma, raw_lambd);
    td_lambda_kernel<<<NBLK + 1, THREADS>>>(values, rewards, dones, out);
}